// round 11
// baseline (speedup 1.0000x reference)
#include <cuda_runtime.h>
#include <math.h>

// Problem constants
#define BB   2
#define SS   2048
#define LL   1024
#define HH   16
#define HKK  4
#define DD   64
#define MROWS (BB*SS)            // 4096
#define QKVN  ((HH + 2*HKK)*DD)  // 1536 (only the used columns of w_qkv)

// Scratch (allocation-free rule: __device__ globals)
__device__ float g_qkv [MROWS * QKVN];   // [4096][1536]: q(1024) | k(256) | v(256)
__device__ float g_attn[MROWS * LL];     // [4096][1024]: attention output, head-major

// ---------------------------------------------------------------------------
// TF32 helpers
// ---------------------------------------------------------------------------
__device__ __forceinline__ unsigned f2tf(float f) {
    unsigned u;
    asm("cvt.rna.tf32.f32 %0, %1;" : "=r"(u) : "f"(f));
    return u;
}

__device__ __forceinline__ uint4 cvt4(float4 v) {
    return make_uint4(f2tf(v.x), f2tf(v.y), f2tf(v.z), f2tf(v.w));
}

__device__ __forceinline__ void mma8(float* c, const unsigned* a, const unsigned* b) {
    asm volatile(
        "mma.sync.aligned.m16n8k8.row.col.f32.tf32.tf32.f32 "
        "{%0,%1,%2,%3}, {%4,%5,%6,%7}, {%8,%9}, {%0,%1,%2,%3};"
        : "+f"(c[0]), "+f"(c[1]), "+f"(c[2]), "+f"(c[3])
        : "r"(a[0]), "r"(a[1]), "r"(a[2]), "r"(a[3]),
          "r"(b[0]), "r"(b[1]));
}

// ---------------------------------------------------------------------------
// TF32 tensor-core GEMM (NT): C[M,N] = A[M,K] * B[N,K]^T   [R7 config: proven]
// 128x128 block, BK=16, 256 threads, warps 2(M)x4(N) -> 64x32 warp tiles,
// 124 regs, 41KB smem, 2 CTAs/SM (16 warps). Stride-20 conflict-free layout.
// ---------------------------------------------------------------------------
#define BKS 20

__device__ __forceinline__
void mma_gemm_nt(const float* __restrict__ A, const float* __restrict__ B,
                 float* __restrict__ C, int N, int K)
{
    __shared__ unsigned As[2][128 * BKS];
    __shared__ unsigned Bs[2][128 * BKS];

    const int bm   = blockIdx.y << 7;
    const int bn   = blockIdx.x << 7;
    const int tid  = threadIdx.x;
    const int lane = tid & 31;
    const int wid  = tid >> 5;
    const int wm   = wid >> 2;     // 0..1
    const int wn   = wid & 3;      // 0..3
    const int g    = lane >> 2;    // 0..7
    const int t4   = lane & 3;     // 0..3

    const int r0 = tid >> 2;             // 0..63
    const int c0 = (tid & 3) << 2;       // 0,4,8,12
    const float* Ag0 = A + (size_t)(bm + r0)      * K + c0;
    const float* Ag1 = A + (size_t)(bm + r0 + 64) * K + c0;
    const float* Bg0 = B + (size_t)(bn + r0)      * K + c0;
    const float* Bg1 = B + (size_t)(bn + r0 + 64) * K + c0;

    float acc[4][4][4];
#pragma unroll
    for (int mt = 0; mt < 4; mt++)
#pragma unroll
        for (int nt = 0; nt < 4; nt++)
#pragma unroll
            for (int r = 0; r < 4; r++) acc[mt][nt][r] = 0.f;

    const int NT = K >> 4;

    float4 va0 = *(const float4*)(Ag0);
    float4 va1 = *(const float4*)(Ag1);
    float4 vb0 = *(const float4*)(Bg0);
    float4 vb1 = *(const float4*)(Bg1);
    {
        *(uint4*)(&As[0][r0 * BKS + c0])        = cvt4(va0);
        *(uint4*)(&As[0][(r0 + 64) * BKS + c0]) = cvt4(va1);
        *(uint4*)(&Bs[0][r0 * BKS + c0])        = cvt4(vb0);
        *(uint4*)(&Bs[0][(r0 + 64) * BKS + c0]) = cvt4(vb1);
    }
    __syncthreads();

    for (int kt = 0; kt < NT; kt++) {
        const int cur = kt & 1;
        if (kt + 1 < NT) {
            const int ko = (kt + 1) << 4;
            va0 = *(const float4*)(Ag0 + ko);
            va1 = *(const float4*)(Ag1 + ko);
            vb0 = *(const float4*)(Bg0 + ko);
            vb1 = *(const float4*)(Bg1 + ko);
        }
        const unsigned* as = As[cur];
        const unsigned* bs = Bs[cur];

#pragma unroll
        for (int ks = 0; ks < 2; ks++) {
            const int kb = ks * 8;
            unsigned af[4][4], bf[4][2];
#pragma unroll
            for (int mt = 0; mt < 4; mt++) {
                const int row = wm * 64 + mt * 16 + g;
                af[mt][0] = as[ row      * BKS + kb + t4];
                af[mt][1] = as[(row + 8) * BKS + kb + t4];
                af[mt][2] = as[ row      * BKS + kb + t4 + 4];
                af[mt][3] = as[(row + 8) * BKS + kb + t4 + 4];
            }
#pragma unroll
            for (int nt = 0; nt < 4; nt++) {
                const int nr = wn * 32 + nt * 8 + g;
                bf[nt][0] = bs[nr * BKS + kb + t4];
                bf[nt][1] = bs[nr * BKS + kb + t4 + 4];
            }
#pragma unroll
            for (int mt = 0; mt < 4; mt++)
#pragma unroll
                for (int nt = 0; nt < 4; nt++)
                    mma8(acc[mt][nt], af[mt], bf[nt]);
        }

        if (kt + 1 < NT) {
            const int nb = (kt + 1) & 1;
            *(uint4*)(&As[nb][r0 * BKS + c0])        = cvt4(va0);
            *(uint4*)(&As[nb][(r0 + 64) * BKS + c0]) = cvt4(va1);
            *(uint4*)(&Bs[nb][r0 * BKS + c0])        = cvt4(vb0);
            *(uint4*)(&Bs[nb][(r0 + 64) * BKS + c0]) = cvt4(vb1);
            __syncthreads();
        }
    }

#pragma unroll
    for (int mt = 0; mt < 4; mt++) {
        const int row = bm + wm * 64 + mt * 16 + g;
#pragma unroll
        for (int nt = 0; nt < 4; nt++) {
            const int col = bn + wn * 32 + nt * 8 + 2 * t4;
            *(float2*)(C + (size_t)row * N + col) =
                make_float2(acc[mt][nt][0], acc[mt][nt][1]);
            *(float2*)(C + (size_t)(row + 8) * N + col) =
                make_float2(acc[mt][nt][2], acc[mt][nt][3]);
        }
    }
}

__global__ __launch_bounds__(256, 2)
void qkv_gemm_kernel(const float* __restrict__ x, const float* __restrict__ w)
{
    mma_gemm_nt(x, w, g_qkv, QKVN, LL);
}

__global__ __launch_bounds__(256, 2)
void out_gemm_kernel(const float* __restrict__ w, float* __restrict__ out)
{
    mma_gemm_nt(g_attn, w, out, LL, LL);
}

// ---------------------------------------------------------------------------
// Flash attention, causal, TF32 tensor cores, v4.
// grid = (S/128, H, B), qb reversed (heavy CTAs first); 128 threads = 4 warps.
// Warp w owns TWO m16 strips (rows 32w..32w+31): every K-fragment and
// V-fragment LDS is shared across both strips (QK: 1.5 LDS/MMA vs 2.5).
// Smem 69KB -> 2 CTAs/SM (8 warps, 512-CTA grid keeps SMs balanced).
// P stays in registers (C-frag -> A-frag quad-shuffle repack).
// ---------------------------------------------------------------------------
#define QTILE 128
#define AST 68
#define VST 72
#define ATTN_SMEM ((QTILE*AST + 64*AST + 64*VST) * 4)   // 70656 B

__global__ __launch_bounds__(128, 2)
void attn_kernel()
{
    extern __shared__ unsigned sm[];
    unsigned* Qs = sm;                         // [128][68], prescaled tf32
    unsigned* Ks = sm + QTILE * AST;           // [64][68]
    unsigned* Vs = Ks + 64 * AST;              // [64][72], row-major V[key][d]

    const int qb   = gridDim.x - 1 - blockIdx.x;   // heavy first
    const int h    = blockIdx.y;
    const int b    = blockIdx.z;
    const int hk   = h >> 2;
    const int tid  = threadIdx.x;
    const int lane = tid & 31;
    const int w    = tid >> 5;            // 0..3
    const int g    = lane >> 2;
    const int t4   = lane & 3;
    const int Rw   = 32 * w;              // warp row base within tile
    const int qrow0 = qb * QTILE + Rw;    // global row base of strip 0

    // ---- load + prescale Q (128x64) ----
    {
        const float* qbase = g_qkv + (size_t)(b * SS + qb * QTILE) * QKVN + h * DD;
#pragma unroll
        for (int i = 0; i < 16; i++) {
            const int e = tid + i * 128;
            const int r = e >> 4, c = (e & 15) << 2;
            float4 v = *(const float4*)(qbase + (size_t)r * QKVN + c);
            *(uint4*)(&Qs[r * AST + c]) =
                make_uint4(f2tf(v.x * 0.125f), f2tf(v.y * 0.125f),
                           f2tf(v.z * 0.125f), f2tf(v.w * 0.125f));
        }
    }

    float m_[2][2], l_[2][2], oacc[2][8][4];
#pragma unroll
    for (int s = 0; s < 2; s++) {
        m_[s][0] = m_[s][1] = -1e30f;
        l_[s][0] = l_[s][1] = 0.f;
#pragma unroll
        for (int nt = 0; nt < 8; nt++)
#pragma unroll
            for (int r = 0; r < 4; r++) oacc[s][nt][r] = 0.f;
    }
    __syncthreads();

    const int kb_max = 2 * qb + 1;
    for (int kb = 0; kb <= kb_max; kb++) {
        // ---- stage K (stride 68) and V (stride 72), 64 keys ----
        const float* kbase = g_qkv + (size_t)(b * SS + kb * 64) * QKVN
                             + HH * DD + hk * DD;
#pragma unroll
        for (int i = 0; i < 8; i++) {
            const int e = tid + i * 128;
            const int r = e >> 4, c = (e & 15) << 2;
            const float* p = kbase + (size_t)r * QKVN + c;
            *(uint4*)(&Ks[r * AST + c]) = cvt4(*(const float4*)(p));
            *(uint4*)(&Vs[r * VST + c]) = cvt4(*(const float4*)(p + HKK * DD));
        }
        __syncthreads();

        const bool act0 = (kb * 64 <= qrow0 + 15);
        const bool act1 = (kb * 64 <= qrow0 + 31);   // act1 >= act0

        if (act1) {
            // ---- S = Q K^T : two m16 strips share every bf load ----
            float sacc[2][8][4];
#pragma unroll
            for (int s = 0; s < 2; s++)
#pragma unroll
                for (int nt = 0; nt < 8; nt++)
#pragma unroll
                    for (int r = 0; r < 4; r++) sacc[s][nt][r] = 0.f;

#pragma unroll
            for (int kk = 0; kk < 8; kk++) {
                const int kp = kk * 8;
                unsigned bf[8][2];
#pragma unroll
                for (int nt = 0; nt < 8; nt++) {
                    bf[nt][0] = Ks[(nt * 8 + g) * AST + kp + t4];
                    bf[nt][1] = Ks[(nt * 8 + g) * AST + kp + t4 + 4];
                }
                {   // strip 1 (always active when act1)
                    const int R = Rw + 16 + g;
                    unsigned af[4];
                    af[0] = Qs[ R      * AST + kp + t4];
                    af[1] = Qs[(R + 8) * AST + kp + t4];
                    af[2] = Qs[ R      * AST + kp + t4 + 4];
                    af[3] = Qs[(R + 8) * AST + kp + t4 + 4];
#pragma unroll
                    for (int nt = 0; nt < 8; nt++)
                        mma8(sacc[1][nt], af, bf[nt]);
                }
                if (act0) {
                    const int R = Rw + g;
                    unsigned af[4];
                    af[0] = Qs[ R      * AST + kp + t4];
                    af[1] = Qs[(R + 8) * AST + kp + t4];
                    af[2] = Qs[ R      * AST + kp + t4 + 4];
                    af[3] = Qs[(R + 8) * AST + kp + t4 + 4];
#pragma unroll
                    for (int nt = 0; nt < 8; nt++)
                        mma8(sacc[0][nt], af, bf[nt]);
                }
            }

            // ---- per-strip mask + online softmax ----
            const bool act[2] = {act0, act1};
#pragma unroll
            for (int s = 0; s < 2; s++) {
                if (!act[s]) continue;
                const int gR = qrow0 + 16 * s + g;

                if (kb * 64 + 63 > qrow0 + 16 * s) {
#pragma unroll
                    for (int nt = 0; nt < 8; nt++) {
                        const int cc = kb * 64 + nt * 8 + 2 * t4;
                        if (cc     > gR)     sacc[s][nt][0] = -1e30f;
                        if (cc + 1 > gR)     sacc[s][nt][1] = -1e30f;
                        if (cc     > gR + 8) sacc[s][nt][2] = -1e30f;
                        if (cc + 1 > gR + 8) sacc[s][nt][3] = -1e30f;
                    }
                }

                float mx0 = -1e30f, mx1 = -1e30f;
#pragma unroll
                for (int nt = 0; nt < 8; nt++) {
                    mx0 = fmaxf(mx0, fmaxf(sacc[s][nt][0], sacc[s][nt][1]));
                    mx1 = fmaxf(mx1, fmaxf(sacc[s][nt][2], sacc[s][nt][3]));
                }
                mx0 = fmaxf(mx0, __shfl_xor_sync(0xffffffffu, mx0, 1));
                mx0 = fmaxf(mx0, __shfl_xor_sync(0xffffffffu, mx0, 2));
                mx1 = fmaxf(mx1, __shfl_xor_sync(0xffffffffu, mx1, 1));
                mx1 = fmaxf(mx1, __shfl_xor_sync(0xffffffffu, mx1, 2));

                const float mn0 = fmaxf(m_[s][0], mx0);
                const float mn1 = fmaxf(m_[s][1], mx1);
                float sum0 = 0.f, sum1 = 0.f;
#pragma unroll
                for (int nt = 0; nt < 8; nt++) {
                    sacc[s][nt][0] = __expf(sacc[s][nt][0] - mn0);
                    sacc[s][nt][1] = __expf(sacc[s][nt][1] - mn0);
                    sacc[s][nt][2] = __expf(sacc[s][nt][2] - mn1);
                    sacc[s][nt][3] = __expf(sacc[s][nt][3] - mn1);
                    sum0 += sacc[s][nt][0] + sacc[s][nt][1];
                    sum1 += sacc[s][nt][2] + sacc[s][nt][3];
                }
                sum0 += __shfl_xor_sync(0xffffffffu, sum0, 1);
                sum0 += __shfl_xor_sync(0xffffffffu, sum0, 2);
                sum1 += __shfl_xor_sync(0xffffffffu, sum1, 1);
                sum1 += __shfl_xor_sync(0xffffffffu, sum1, 2);

                const float a0 = __expf(m_[s][0] - mn0);
                const float a1 = __expf(m_[s][1] - mn1);
                l_[s][0] = l_[s][0] * a0 + sum0;  m_[s][0] = mn0;
                l_[s][1] = l_[s][1] * a1 + sum1;  m_[s][1] = mn1;
#pragma unroll
                for (int nt = 0; nt < 8; nt++) {
                    oacc[s][nt][0] *= a0; oacc[s][nt][1] *= a0;
                    oacc[s][nt][2] *= a1; oacc[s][nt][3] *= a1;
                }
            }

            // ---- O += P*V : V fragments shared across strips ----
            const int sA = (lane & ~3) | (t4 >> 1);
            const int sB = sA + 2;
            const bool odd = (t4 & 1);
#pragma unroll
            for (int kk = 0; kk < 8; kk++) {
                const int kp = kk * 8;
                unsigned bf[8][2];
#pragma unroll
                for (int nt = 0; nt < 8; nt++) {
                    bf[nt][0] = Vs[(kp + t4)     * VST + nt * 8 + g];
                    bf[nt][1] = Vs[(kp + t4 + 4) * VST + nt * 8 + g];
                }
#pragma unroll
                for (int s = 0; s < 2; s++) {
                    if (!act[s]) continue;
                    float v0A = __shfl_sync(0xffffffffu, sacc[s][kk][0], sA);
                    float v1A = __shfl_sync(0xffffffffu, sacc[s][kk][1], sA);
                    float v2A = __shfl_sync(0xffffffffu, sacc[s][kk][2], sA);
                    float v3A = __shfl_sync(0xffffffffu, sacc[s][kk][3], sA);
                    float v0B = __shfl_sync(0xffffffffu, sacc[s][kk][0], sB);
                    float v1B = __shfl_sync(0xffffffffu, sacc[s][kk][1], sB);
                    float v2B = __shfl_sync(0xffffffffu, sacc[s][kk][2], sB);
                    float v3B = __shfl_sync(0xffffffffu, sacc[s][kk][3], sB);
                    unsigned af[4];
                    af[0] = f2tf(odd ? v1A : v0A);
                    af[1] = f2tf(odd ? v3A : v2A);
                    af[2] = f2tf(odd ? v1B : v0B);
                    af[3] = f2tf(odd ? v3B : v2B);
#pragma unroll
                    for (int nt = 0; nt < 8; nt++)
                        mma8(oacc[s][nt], af, bf[nt]);
                }
            }
        }
        __syncthreads();   // before next iteration overwrites Ks/Vs
    }

    // ---- normalize + store (head-major [b,s,h,d]) ----
    float* ob = g_attn + (size_t)(b * SS + qb * QTILE) * LL + h * DD;
#pragma unroll
    for (int s = 0; s < 2; s++) {
        const int R = Rw + 16 * s + g;
        const float inv0 = 1.f / l_[s][0];
        const float inv1 = 1.f / l_[s][1];
#pragma unroll
        for (int nt = 0; nt < 8; nt++) {
            const int cc = nt * 8 + 2 * t4;
            *(float2*)(ob + (size_t)R * LL + cc) =
                make_float2(oacc[s][nt][0] * inv0, oacc[s][nt][1] * inv0);
            *(float2*)(ob + (size_t)(R + 8) * LL + cc) =
                make_float2(oacc[s][nt][2] * inv1, oacc[s][nt][3] * inv1);
        }
    }
}

// ---------------------------------------------------------------------------
extern "C" void kernel_launch(void* const* d_in, const int* in_sizes, int n_in,
                              void* d_out, int out_size)
{
    const float* x = nullptr;
    const float* w_qkv = nullptr;
    const float* w_out = nullptr;
    for (int i = 0; i < n_in; i++) {
        if      (in_sizes[i] == 4194304) x     = (const float*)d_in[i];
        else if (in_sizes[i] == 3670016) w_qkv = (const float*)d_in[i];
        else if (in_sizes[i] == 1048576) w_out = (const float*)d_in[i];
    }
    float* out = (float*)d_out;

    static bool attr_set = false;
    if (!attr_set) {
        cudaFuncSetAttribute(attn_kernel,
                             cudaFuncAttributeMaxDynamicSharedMemorySize,
                             ATTN_SMEM);
        attr_set = true;
    }

    // 1) fused QKV projection (only the 1536 columns actually consumed)
    qkv_gemm_kernel<<<dim3(QKVN / 128, MROWS / 128), 256>>>(x, w_qkv);

    // 2) causal GQA flash attention (tf32 tensor cores, dual-strip warps)
    attn_kernel<<<dim3(SS / QTILE, HH, BB), 128, ATTN_SMEM>>>();

    // 3) output projection
    out_gemm_kernel<<<dim3(LL / 128, MROWS / 128), 256>>>(w_out, out);
}

// round 13
// speedup vs baseline: 1.0647x; 1.0647x over previous
#include <cuda_runtime.h>
#include <math.h>
#include <stdint.h>

// Problem constants
#define BB   2
#define SS   2048
#define LL   1024
#define HH   16
#define HKK  4
#define DD   64
#define MROWS (BB*SS)            // 4096
#define QKVN  ((HH + 2*HKK)*DD)  // 1536 (only the used columns of w_qkv)

// Scratch (allocation-free rule: __device__ globals). All tf32-in-u32.
__device__ unsigned g_x32 [MROWS * LL];     // x converted to tf32
__device__ unsigned g_w1  [QKVN * LL];      // w_qkv[0:1536] converted
__device__ unsigned g_w2  [LL * LL];        // w_out converted
__device__ unsigned g_qkv [MROWS * QKVN];   // qkv proj (Q cols pre-scaled), tf32
__device__ unsigned g_attn[MROWS * LL];     // attention output, tf32

// ---------------------------------------------------------------------------
// TF32 / cp.async helpers
// ---------------------------------------------------------------------------
__device__ __forceinline__ unsigned f2tf(float f) {
    unsigned u;
    asm("cvt.rna.tf32.f32 %0, %1;" : "=r"(u) : "f"(f));
    return u;
}

__device__ __forceinline__ void mma8(float* c, const unsigned* a, const unsigned* b) {
    asm volatile(
        "mma.sync.aligned.m16n8k8.row.col.f32.tf32.tf32.f32 "
        "{%0,%1,%2,%3}, {%4,%5,%6,%7}, {%8,%9}, {%0,%1,%2,%3};"
        : "+f"(c[0]), "+f"(c[1]), "+f"(c[2]), "+f"(c[3])
        : "r"(a[0]), "r"(a[1]), "r"(a[2]), "r"(a[3]),
          "r"(b[0]), "r"(b[1]));
}

__device__ __forceinline__ uint32_t smem_u32(const void* p) {
    uint32_t a;
    asm("{ .reg .u64 t; cvta.to.shared.u64 t, %1; cvt.u32.u64 %0, t; }"
        : "=r"(a) : "l"(p));
    return a;
}

__device__ __forceinline__ void cp16(uint32_t dst, const void* src) {
    asm volatile("cp.async.cg.shared.global [%0], [%1], 16;"
                 :: "r"(dst), "l"(src));
}
#define CP_COMMIT() asm volatile("cp.async.commit_group;" ::: "memory")
#define CP_WAIT0()  asm volatile("cp.async.wait_group 0;"  ::: "memory")

// ---------------------------------------------------------------------------
// One-time fp32 -> tf32 conversion (grid-stride-free exact cover, n % 1024 == 0)
// ---------------------------------------------------------------------------
__global__ __launch_bounds__(256)
void cvt_kernel(const float* __restrict__ src, unsigned* __restrict__ dst)
{
    const int i = (blockIdx.x * 256 + threadIdx.x) * 4;
    float4 v = *(const float4*)(src + i);
    *(uint4*)(dst + i) = make_uint4(f2tf(v.x), f2tf(v.y), f2tf(v.z), f2tf(v.w));
}

// ---------------------------------------------------------------------------
// TF32 tensor-core GEMM (NT): C = A * B^T, A/B already tf32-in-u32.
// 128x128 block, BK=16, 256 threads, warps 2(M)x4(N) -> 64x32 warp tiles.
// Staging is pure cp.async (no LDG/cvt/STS in the hot loop).
// Stride-20 smem rows: fragment LDS banks (20g+t4) mod 32 all distinct.
// MODE_TF32OUT: emit tf32 u32 (Q cols x<1024 pre-scaled by 0.125).
// ---------------------------------------------------------------------------
#define BKS 20

template <bool TF32OUT>
__device__ __forceinline__
void mma_gemm_nt(const unsigned* __restrict__ A, const unsigned* __restrict__ B,
                 void* __restrict__ C, int N, int K)
{
    __shared__ unsigned As[2][128 * BKS];
    __shared__ unsigned Bs[2][128 * BKS];

    const int bm   = blockIdx.y << 7;
    const int bn   = blockIdx.x << 7;
    const int tid  = threadIdx.x;
    const int lane = tid & 31;
    const int wid  = tid >> 5;
    const int wm   = wid >> 2;     // 0..1
    const int wn   = wid & 3;      // 0..3
    const int g    = lane >> 2;    // 0..7
    const int t4   = lane & 3;     // 0..3

    const int r0 = tid >> 2;             // 0..63
    const int c0 = (tid & 3) << 2;       // 0,4,8,12
    const unsigned* Ag0 = A + (size_t)(bm + r0)      * K + c0;
    const unsigned* Ag1 = A + (size_t)(bm + r0 + 64) * K + c0;
    const unsigned* Bg0 = B + (size_t)(bn + r0)      * K + c0;
    const unsigned* Bg1 = B + (size_t)(bn + r0 + 64) * K + c0;

    const uint32_t asb = smem_u32(As) + (r0 * BKS + c0) * 4;
    const uint32_t bsb = smem_u32(Bs) + (r0 * BKS + c0) * 4;
    const uint32_t bufB = 128 * BKS * 4;
    const uint32_t row64 = 64 * BKS * 4;

    float acc[4][4][4];
#pragma unroll
    for (int mt = 0; mt < 4; mt++)
#pragma unroll
        for (int nt = 0; nt < 4; nt++)
#pragma unroll
            for (int r = 0; r < 4; r++) acc[mt][nt][r] = 0.f;

    const int NT = K >> 4;

    // stage tile 0
    cp16(asb,         Ag0);
    cp16(asb + row64, Ag1);
    cp16(bsb,         Bg0);
    cp16(bsb + row64, Bg1);
    CP_COMMIT();
    CP_WAIT0();
    __syncthreads();

    for (int kt = 0; kt < NT; kt++) {
        const int cur = kt & 1;
        if (kt + 1 < NT) {
            const int ko = (kt + 1) << 4;
            const uint32_t off = ((kt + 1) & 1) * bufB;
            cp16(asb + off,         Ag0 + ko);
            cp16(asb + off + row64, Ag1 + ko);
            cp16(bsb + off,         Bg0 + ko);
            cp16(bsb + off + row64, Bg1 + ko);
            CP_COMMIT();
        }
        const unsigned* as = As[cur];
        const unsigned* bs = Bs[cur];

#pragma unroll
        for (int ks = 0; ks < 2; ks++) {
            const int kb = ks * 8;
            unsigned af[4][4], bf[4][2];
#pragma unroll
            for (int mt = 0; mt < 4; mt++) {
                const int row = wm * 64 + mt * 16 + g;
                af[mt][0] = as[ row      * BKS + kb + t4];
                af[mt][1] = as[(row + 8) * BKS + kb + t4];
                af[mt][2] = as[ row      * BKS + kb + t4 + 4];
                af[mt][3] = as[(row + 8) * BKS + kb + t4 + 4];
            }
#pragma unroll
            for (int nt = 0; nt < 4; nt++) {
                const int nr = wn * 32 + nt * 8 + g;
                bf[nt][0] = bs[nr * BKS + kb + t4];
                bf[nt][1] = bs[nr * BKS + kb + t4 + 4];
            }
#pragma unroll
            for (int mt = 0; mt < 4; mt++)
#pragma unroll
                for (int nt = 0; nt < 4; nt++)
                    mma8(acc[mt][nt], af[mt], bf[nt]);
        }

        if (kt + 1 < NT) {
            CP_WAIT0();
            __syncthreads();
        }
    }

    if (TF32OUT) {
        // Q columns (< 1024 in qkv layout) are pre-scaled by 1/sqrt(D)=0.125.
        const float s = (bn < 1024) ? 0.125f : 1.0f;
        unsigned* Cu = (unsigned*)C;
#pragma unroll
        for (int mt = 0; mt < 4; mt++) {
            const int row = bm + wm * 64 + mt * 16 + g;
#pragma unroll
            for (int nt = 0; nt < 4; nt++) {
                const int col = bn + wn * 32 + nt * 8 + 2 * t4;
                *(uint2*)(Cu + (size_t)row * N + col) =
                    make_uint2(f2tf(acc[mt][nt][0] * s), f2tf(acc[mt][nt][1] * s));
                *(uint2*)(Cu + (size_t)(row + 8) * N + col) =
                    make_uint2(f2tf(acc[mt][nt][2] * s), f2tf(acc[mt][nt][3] * s));
            }
        }
    } else {
        float* Cf = (float*)C;
#pragma unroll
        for (int mt = 0; mt < 4; mt++) {
            const int row = bm + wm * 64 + mt * 16 + g;
#pragma unroll
            for (int nt = 0; nt < 4; nt++) {
                const int col = bn + wn * 32 + nt * 8 + 2 * t4;
                *(float2*)(Cf + (size_t)row * N + col) =
                    make_float2(acc[mt][nt][0], acc[mt][nt][1]);
                *(float2*)(Cf + (size_t)(row + 8) * N + col) =
                    make_float2(acc[mt][nt][2], acc[mt][nt][3]);
            }
        }
    }
}

__global__ __launch_bounds__(256, 2)
void qkv_gemm_kernel()
{
    mma_gemm_nt<true>(g_x32, g_w1, g_qkv, QKVN, LL);
}

__global__ __launch_bounds__(256, 2)
void out_gemm_kernel(float* __restrict__ out)
{
    mma_gemm_nt<false>(g_attn, g_w2, out, LL, LL);
}

// ---------------------------------------------------------------------------
// Flash attention, causal, TF32 tensor cores  [R7 config + cp.async staging]
// grid = (S/128, H, B) qb reversed; 256 threads = 8 warps, warp w owns rows
// 16w..16w+15 (one m16 strip, all 64 columns). Q/K/V already tf32 in g_qkv
// (Q pre-scaled) -> staging is pure cp.async. P stays in registers via
// quad-shuffle C->A repack. Smem 69KB -> 2 CTAs/SM.
// ---------------------------------------------------------------------------
#define QTILE 128
#define AST 68
#define VST 72
#define ATTN_SMEM ((QTILE*AST + 64*AST + 64*VST) * 4)

__global__ __launch_bounds__(256, 2)
void attn_kernel()
{
    extern __shared__ unsigned sm[];
    unsigned* Qs = sm;                         // [128][68], tf32 (pre-scaled)
    unsigned* Ks = sm + QTILE * AST;           // [64][68]
    unsigned* Vs = Ks + 64 * AST;              // [64][72], row-major V[key][d]

    const uint32_t qs_b = smem_u32(Qs);
    const uint32_t ks_b = smem_u32(Ks);
    const uint32_t vs_b = smem_u32(Vs);

    const int qb   = gridDim.x - 1 - blockIdx.x;   // heavy first
    const int h    = blockIdx.y;
    const int b    = blockIdx.z;
    const int hk   = h >> 2;
    const int tid  = threadIdx.x;
    const int lane = tid & 31;
    const int w    = tid >> 5;
    const int g    = lane >> 2;
    const int t4   = lane & 3;
    const int R0   = 16 * w + g;          // fragment row (R1 = R0 + 8)
    const int gR0  = qb * QTILE + R0;     // global query row

    // ---- stage Q (tf32, pre-scaled) via cp.async ----
    {
        const unsigned* qbase = g_qkv + (size_t)(b * SS + qb * QTILE) * QKVN + h * DD;
#pragma unroll
        for (int i = 0; i < 8; i++) {
            const int e = tid + i * 256;
            const int r = e >> 4, c = (e & 15) << 2;
            cp16(qs_b + (r * AST + c) * 4, qbase + (size_t)r * QKVN + c);
        }
        CP_COMMIT();
    }

    float m0 = -1e30f, m1 = -1e30f, l0 = 0.f, l1 = 0.f;
    float oacc[8][4];
#pragma unroll
    for (int nt = 0; nt < 8; nt++)
#pragma unroll
        for (int r = 0; r < 4; r++) oacc[nt][r] = 0.f;

    const int kb_max = 2 * qb + 1;
    for (int kb = 0; kb <= kb_max; kb++) {
        // ---- stage K (stride 68) and V (stride 72) via cp.async ----
        const unsigned* kbase = g_qkv + (size_t)(b * SS + kb * 64) * QKVN
                                + HH * DD + hk * DD;
#pragma unroll
        for (int i = 0; i < 4; i++) {
            const int e = tid + i * 256;
            const int r = e >> 4, c = (e & 15) << 2;
            const unsigned* p = kbase + (size_t)r * QKVN + c;
            cp16(ks_b + (r * AST + c) * 4, p);
            cp16(vs_b + (r * VST + c) * 4, p + HKK * DD);
        }
        CP_COMMIT();
        CP_WAIT0();          // covers Q on first iteration too
        __syncthreads();

        const bool active = (kb * 64 <= qb * QTILE + 16 * w + 15);
        if (active) {
            // ---- S = Q K^T (m16 x n64 per warp) ----
            float sacc[8][4];
#pragma unroll
            for (int nt = 0; nt < 8; nt++)
#pragma unroll
                for (int r = 0; r < 4; r++) sacc[nt][r] = 0.f;

#pragma unroll
            for (int kk = 0; kk < 8; kk++) {
                const int kp = kk * 8;
                unsigned af[4];
                af[0] = Qs[ R0      * AST + kp + t4];
                af[1] = Qs[(R0 + 8) * AST + kp + t4];
                af[2] = Qs[ R0      * AST + kp + t4 + 4];
                af[3] = Qs[(R0 + 8) * AST + kp + t4 + 4];
#pragma unroll
                for (int nt = 0; nt < 8; nt++) {
                    unsigned bf[2];
                    bf[0] = Ks[(nt * 8 + g) * AST + kp + t4];
                    bf[1] = Ks[(nt * 8 + g) * AST + kp + t4 + 4];
                    mma8(sacc[nt], af, bf);
                }
            }

            // ---- causal mask ----
            if (kb * 64 + 63 > qb * QTILE + 16 * w) {
#pragma unroll
                for (int nt = 0; nt < 8; nt++) {
                    const int cc = kb * 64 + nt * 8 + 2 * t4;
                    if (cc     > gR0)     sacc[nt][0] = -1e30f;
                    if (cc + 1 > gR0)     sacc[nt][1] = -1e30f;
                    if (cc     > gR0 + 8) sacc[nt][2] = -1e30f;
                    if (cc + 1 > gR0 + 8) sacc[nt][3] = -1e30f;
                }
            }

            // ---- online softmax ----
            float mx0 = -1e30f, mx1 = -1e30f;
#pragma unroll
            for (int nt = 0; nt < 8; nt++) {
                mx0 = fmaxf(mx0, fmaxf(sacc[nt][0], sacc[nt][1]));
                mx1 = fmaxf(mx1, fmaxf(sacc[nt][2], sacc[nt][3]));
            }
            mx0 = fmaxf(mx0, __shfl_xor_sync(0xffffffffu, mx0, 1));
            mx0 = fmaxf(mx0, __shfl_xor_sync(0xffffffffu, mx0, 2));
            mx1 = fmaxf(mx1, __shfl_xor_sync(0xffffffffu, mx1, 1));
            mx1 = fmaxf(mx1, __shfl_xor_sync(0xffffffffu, mx1, 2));

            const float mn0 = fmaxf(m0, mx0);
            const float mn1 = fmaxf(m1, mx1);
            float sum0 = 0.f, sum1 = 0.f;
#pragma unroll
            for (int nt = 0; nt < 8; nt++) {
                sacc[nt][0] = __expf(sacc[nt][0] - mn0);
                sacc[nt][1] = __expf(sacc[nt][1] - mn0);
                sacc[nt][2] = __expf(sacc[nt][2] - mn1);
                sacc[nt][3] = __expf(sacc[nt][3] - mn1);
                sum0 += sacc[nt][0] + sacc[nt][1];
                sum1 += sacc[nt][2] + sacc[nt][3];
            }
            sum0 += __shfl_xor_sync(0xffffffffu, sum0, 1);
            sum0 += __shfl_xor_sync(0xffffffffu, sum0, 2);
            sum1 += __shfl_xor_sync(0xffffffffu, sum1, 1);
            sum1 += __shfl_xor_sync(0xffffffffu, sum1, 2);

            const float a0 = __expf(m0 - mn0);
            const float a1 = __expf(m1 - mn1);
            l0 = l0 * a0 + sum0;  m0 = mn0;
            l1 = l1 * a1 + sum1;  m1 = mn1;
#pragma unroll
            for (int nt = 0; nt < 8; nt++) {
                oacc[nt][0] *= a0; oacc[nt][1] *= a0;
                oacc[nt][2] *= a1; oacc[nt][3] *= a1;
            }

            // ---- O += P*V (register repack via quad shuffles) ----
            const int sA = (lane & ~3) | (t4 >> 1);
            const int sB = sA + 2;
            const bool odd = (t4 & 1);
#pragma unroll
            for (int kk = 0; kk < 8; kk++) {
                float v0A = __shfl_sync(0xffffffffu, sacc[kk][0], sA);
                float v1A = __shfl_sync(0xffffffffu, sacc[kk][1], sA);
                float v2A = __shfl_sync(0xffffffffu, sacc[kk][2], sA);
                float v3A = __shfl_sync(0xffffffffu, sacc[kk][3], sA);
                float v0B = __shfl_sync(0xffffffffu, sacc[kk][0], sB);
                float v1B = __shfl_sync(0xffffffffu, sacc[kk][1], sB);
                float v2B = __shfl_sync(0xffffffffu, sacc[kk][2], sB);
                float v3B = __shfl_sync(0xffffffffu, sacc[kk][3], sB);
                unsigned af[4];
                af[0] = f2tf(odd ? v1A : v0A);
                af[1] = f2tf(odd ? v3A : v2A);
                af[2] = f2tf(odd ? v1B : v0B);
                af[3] = f2tf(odd ? v3B : v2B);
                const int kp = kk * 8;
#pragma unroll
                for (int nt = 0; nt < 8; nt++) {
                    unsigned bf[2];
                    bf[0] = Vs[(kp + t4)     * VST + nt * 8 + g];
                    bf[1] = Vs[(kp + t4 + 4) * VST + nt * 8 + g];
                    mma8(oacc[nt], af, bf);
                }
            }
        }
        __syncthreads();
    }

    // ---- normalize + store tf32 (head-major [b,s,h,d]) ----
    const float inv0 = 1.f / l0;
    const float inv1 = 1.f / l1;
    unsigned* ob = g_attn + (size_t)(b * SS + qb * QTILE) * LL + h * DD;
#pragma unroll
    for (int nt = 0; nt < 8; nt++) {
        const int cc = nt * 8 + 2 * t4;
        *(uint2*)(ob + (size_t)R0 * LL + cc) =
            make_uint2(f2tf(oacc[nt][0] * inv0), f2tf(oacc[nt][1] * inv0));
        *(uint2*)(ob + (size_t)(R0 + 8) * LL + cc) =
            make_uint2(f2tf(oacc[nt][2] * inv1), f2tf(oacc[nt][3] * inv1));
    }
}

// ---------------------------------------------------------------------------
extern "C" void kernel_launch(void* const* d_in, const int* in_sizes, int n_in,
                              void* d_out, int out_size)
{
    const float* x = nullptr;
    const float* w_qkv = nullptr;
    const float* w_out = nullptr;
    for (int i = 0; i < n_in; i++) {
        if      (in_sizes[i] == 4194304) x     = (const float*)d_in[i];
        else if (in_sizes[i] == 3670016) w_qkv = (const float*)d_in[i];
        else if (in_sizes[i] == 1048576) w_out = (const float*)d_in[i];
    }
    float* out = (float*)d_out;

    static bool attr_set = false;
    if (!attr_set) {
        cudaFuncSetAttribute(attn_kernel,
                             cudaFuncAttributeMaxDynamicSharedMemorySize,
                             ATTN_SMEM);
        attr_set = true;
    }

    unsigned* d_x32; cudaGetSymbolAddress((void**)&d_x32, g_x32);
    unsigned* d_w1;  cudaGetSymbolAddress((void**)&d_w1,  g_w1);
    unsigned* d_w2;  cudaGetSymbolAddress((void**)&d_w2,  g_w2);

    // 0) one-time tf32 conversion of inputs (bit-identical rna rounding)
    cvt_kernel<<<(MROWS * LL) / 1024, 256>>>(x, d_x32);
    cvt_kernel<<<(QKVN  * LL) / 1024, 256>>>(w_qkv, d_w1);
    cvt_kernel<<<(LL    * LL) / 1024, 256>>>(w_out, d_w2);

    // 1) fused QKV projection -> g_qkv (tf32, Q pre-scaled)
    qkv_gemm_kernel<<<dim3(QKVN / 128, MROWS / 128), 256>>>();

    // 2) causal GQA flash attention -> g_attn (tf32)
    attn_kernel<<<dim3(SS / QTILE, HH, BB), 256, ATTN_SMEM>>>();

    // 3) output projection -> out (fp32)
    out_gemm_kernel<<<dim3(LL / 128, MROWS / 128), 256>>>(out);
}